// round 13
// baseline (speedup 1.0000x reference)
#include <cuda_runtime.h>
#include <cstdint>

#define B_  8
#define S_  1024
#define D_  1024
#define H_  16
#define DH_ 64
#define BSD_ (B_ * S_ * D_)
#define BHS_ (B_ * H_ * S_)
#define SCALE_ 0.125f

// ---------------------------------------------------------------------------
// Scratch (__device__ globals; alloc-free rule)
// ---------------------------------------------------------------------------
__device__ float g_q[BSD_];
__device__ float g_k[BSD_];
__device__ float g_v[BSD_];
__device__ float g_ctx[BSD_];
__device__ float g_rowsum[BHS_];
__device__ float g_rxq[BSD_];          // tf32-rounded query
__device__ float g_rxk[BSD_];          // tf32-rounded key
__device__ float g_rxv[BSD_];          // tf32-rounded value
__device__ float g_rw[4 * D_ * D_];    // tf32-rounded Wq,Wk,Wv,Wo
__device__ float g_attn_fb[(size_t)B_ * H_ * S_ * S_];  // fallback attn sink

// ---------------------------------------------------------------------------
// Helpers
// ---------------------------------------------------------------------------
__device__ __forceinline__ float to_tf32(float x) {
    uint32_t u;
    asm("cvt.rna.tf32.f32 %0, %1;" : "=r"(u) : "f"(x));
    return __uint_as_float(u);
}

__device__ __forceinline__ void mma_tf32(float c[4],
                                         const float a[4], const float b[2]) {
    uint32_t a0 = __float_as_uint(a[0]), a1 = __float_as_uint(a[1]);
    uint32_t a2 = __float_as_uint(a[2]), a3 = __float_as_uint(a[3]);
    uint32_t b0 = __float_as_uint(b[0]), b1 = __float_as_uint(b[1]);
    asm volatile(
        "mma.sync.aligned.m16n8k8.row.col.f32.tf32.tf32.f32 "
        "{%0,%1,%2,%3}, {%4,%5,%6,%7}, {%8,%9}, {%0,%1,%2,%3};"
        : "+f"(c[0]), "+f"(c[1]), "+f"(c[2]), "+f"(c[3])
        : "r"(a0), "r"(a1), "r"(a2), "r"(a3), "r"(b0), "r"(b1));
}

__device__ __forceinline__ void cpa16(uint32_t dst, const void* src) {
    asm volatile("cp.async.cg.shared.global [%0], [%1], 16;\n" :: "r"(dst), "l"(src));
}
__device__ __forceinline__ void cp_commit() { asm volatile("cp.async.commit_group;\n"); }
__device__ __forceinline__ void cp_wait0()  { asm volatile("cp.async.wait_group 0;\n"); }
__device__ __forceinline__ void cp_wait1()  { asm volatile("cp.async.wait_group 1;\n"); }
__device__ __forceinline__ void cp_wait2()  { asm volatile("cp.async.wait_group 2;\n"); }

// ---------------------------------------------------------------------------
// Elementwise tf32 rounding prepass (memory-bound, ~11us per 33MB)
// ---------------------------------------------------------------------------
__global__ __launch_bounds__(256)
void cvt_rna_kernel(const float4* __restrict__ in, float4* __restrict__ out, int n4) {
    int i = blockIdx.x * 256 + threadIdx.x;
    if (i < n4) {
        float4 v = in[i];
        v.x = to_tf32(v.x); v.y = to_tf32(v.y);
        v.z = to_tf32(v.z); v.w = to_tf32(v.w);
        out[i] = v;
    }
}

// ---------------------------------------------------------------------------
// Projection GEMM: C[8192,1024] = A @ W + bias. BM=128, BN=128, BK=32,
// 3-stage cp.async. A/W MUST be pre-rounded tf32 (no inner-loop cvts).
// ---------------------------------------------------------------------------
#define PA_ST (128 * 36)
#define PB_ST (32 * 136)

__device__ __forceinline__ void proj_load_stage(
    uint32_t asb, uint32_t bsb, const float* A, const float* W,
    int row0, int col0, int k0, int st, int t) {
    #pragma unroll
    for (int i = 0; i < 4; i++) {
        int idx = t + i * 256;
        int m = idx >> 3, c = idx & 7;
        cpa16(asb + (uint32_t)((st * PA_ST + m * 36 + c * 4) * 4),
              A + (size_t)(row0 + m) * D_ + k0 + c * 4);
    }
    #pragma unroll
    for (int i = 0; i < 4; i++) {
        int idx = t + i * 256;
        int k = idx >> 5, c = idx & 31;
        cpa16(bsb + (uint32_t)((st * PB_ST + k * 136 + c * 4) * 4),
              W + (size_t)(k0 + k) * D_ + col0 + c * 4);
    }
    cp_commit();
}

template<bool ROUND>
__global__ __launch_bounds__(256)
void proj_gemm(const float* __restrict__ A, const float* __restrict__ W,
               const float* __restrict__ bias, float* __restrict__ C) {
    extern __shared__ float sm[];
    float* As = sm;
    float* Bs = sm + 3 * PA_ST;
    const int t = threadIdx.x;
    const int row0 = blockIdx.y * 128, col0 = blockIdx.x * 128;
    const uint32_t asb = (uint32_t)__cvta_generic_to_shared(As);
    const uint32_t bsb = (uint32_t)__cvta_generic_to_shared(Bs);

    const int lane = t & 31, warp = t >> 5;
    const int wm = (warp >> 2) * 64, wn = (warp & 3) * 32;
    const int qr = lane >> 2, qc = lane & 3;

    float acc[4][4][4] = {};

    proj_load_stage(asb, bsb, A, W, row0, col0, 0, 0, t);
    proj_load_stage(asb, bsb, A, W, row0, col0, 32, 1, t);

    for (int kt = 0; kt < 32; kt++) {
        if (kt < 30) {
            proj_load_stage(asb, bsb, A, W, row0, col0, (kt + 2) * 32, (kt + 2) % 3, t);
            cp_wait2();
        } else if (kt == 30) {
            cp_wait1();
        } else {
            cp_wait0();
        }
        __syncthreads();

        const float* as = As + (kt % 3) * PA_ST;
        const float* bs = Bs + (kt % 3) * PB_ST;
        #pragma unroll
        for (int ks = 0; ks < 4; ks++) {
            const int kb = ks * 8;
            float a[4][4], b[4][2];
            #pragma unroll
            for (int mt = 0; mt < 4; mt++) {
                const float* ap = as + (wm + mt * 16 + qr) * 36 + kb + qc;
                a[mt][0] = ap[0];        a[mt][1] = ap[8 * 36];
                a[mt][2] = ap[4];        a[mt][3] = ap[8 * 36 + 4];
            }
            #pragma unroll
            for (int nt = 0; nt < 4; nt++) {
                const float* bp = bs + (kb + qc) * 136 + wn + nt * 8 + qr;
                b[nt][0] = bp[0];        b[nt][1] = bp[4 * 136];
            }
            #pragma unroll
            for (int mt = 0; mt < 4; mt++)
                #pragma unroll
                for (int nt = 0; nt < 4; nt++)
                    mma_tf32(acc[mt][nt], a[mt], b[nt]);
        }
        __syncthreads();
    }

    #pragma unroll
    for (int mt = 0; mt < 4; mt++) {
        #pragma unroll
        for (int nt = 0; nt < 4; nt++) {
            const int r = row0 + wm + mt * 16 + qr;
            const int c = col0 + wn + nt * 8 + 2 * qc;
            const float b0 = bias[c], b1 = bias[c + 1];
            float v0 = acc[mt][nt][0] + b0, v1 = acc[mt][nt][1] + b1;
            float v2 = acc[mt][nt][2] + b0, v3 = acc[mt][nt][3] + b1;
            if (ROUND) {
                v0 = to_tf32(v0); v1 = to_tf32(v1);
                v2 = to_tf32(v2); v3 = to_tf32(v3);
            }
            *(float2*)(C + (size_t)r * D_ + c)       = make_float2(v0, v1);
            *(float2*)(C + (size_t)(r + 8) * D_ + c) = make_float2(v2, v3);
        }
    }
}

// ---------------------------------------------------------------------------
// Pass A: rowsum[z,i] = sum_j exp(scale * q_i . k_j). Q (128 rows) resident,
// K in 64-row double-buffered tiles. Inputs pre-rounded (proj epilogue).
// ---------------------------------------------------------------------------
#define RK_ST (64 * 68)

__global__ __launch_bounds__(256, 2)
void rowsum_kernel(const float* __restrict__ Q, const float* __restrict__ K,
                   float* __restrict__ rowsum) {
    extern __shared__ float sm[];
    float* Qs  = sm;                          // [128][68]
    float* Ks  = sm + 128 * 68;              // 2 x [64][68]
    float* prt = sm + 128 * 68 + 2 * RK_ST;  // [2][128]

    const int z = blockIdx.y;
    const size_t ho = (size_t)(z >> 4) * S_ * D_ + (size_t)(z & 15) * DH_;
    const float* Qg = Q + ho;
    const float* Kg = K + ho;
    const int t = threadIdx.x;
    const int row0 = blockIdx.x * 128;
    const uint32_t qsb = (uint32_t)__cvta_generic_to_shared(Qs);
    const uint32_t ksb = (uint32_t)__cvta_generic_to_shared(Ks);

    prt[t] = 0.f;

    #pragma unroll
    for (int i = 0; i < 8; i++) {
        int idx = t + i * 256;
        int m = idx >> 4, c = idx & 15;
        cpa16(qsb + (uint32_t)((m * 68 + c * 4) * 4),
              Qg + (size_t)(row0 + m) * D_ + c * 4);
    }
    #pragma unroll
    for (int i = 0; i < 4; i++) {
        int idx = t + i * 256;
        int n = idx >> 4, c = idx & 15;
        cpa16(ksb + (uint32_t)((n * 68 + c * 4) * 4),
              Kg + (size_t)n * D_ + c * 4);
    }
    cp_commit();

    const int lane = t & 31, warp = t >> 5;
    const int wm = (warp >> 1) * 32;
    const int wj = (warp & 1) * 32;
    const int qr = lane >> 2, qc = lane & 3;

    float prs[2][2] = {};

    for (int jt = 0; jt < 16; jt++) {
        if (jt < 15) {
            const int st = (jt + 1) & 1;
            #pragma unroll
            for (int i = 0; i < 4; i++) {
                int idx = t + i * 256;
                int n = idx >> 4, c = idx & 15;
                cpa16(ksb + (uint32_t)((st * RK_ST + n * 68 + c * 4) * 4),
                      Kg + (size_t)((jt + 1) * 64 + n) * D_ + c * 4);
            }
            cp_commit();
            cp_wait1();
        } else {
            cp_wait0();
        }
        __syncthreads();

        const float* ks_ = Ks + (jt & 1) * RK_ST;
        float acc[2][4][4] = {};
        #pragma unroll
        for (int ks = 0; ks < 8; ks++) {
            const int kb = ks * 8;
            float a[2][4], b[4][2];
            #pragma unroll
            for (int mt = 0; mt < 2; mt++) {
                const float* ap = Qs + (wm + mt * 16 + qr) * 68 + kb + qc;
                a[mt][0] = ap[0];       a[mt][1] = ap[8 * 68];
                a[mt][2] = ap[4];       a[mt][3] = ap[8 * 68 + 4];
            }
            #pragma unroll
            for (int nt = 0; nt < 4; nt++) {
                const float* bp = ks_ + (wj + nt * 8 + qr) * 68 + kb + qc;
                b[nt][0] = bp[0];       b[nt][1] = bp[4];
            }
            #pragma unroll
            for (int mt = 0; mt < 2; mt++)
                #pragma unroll
                for (int nt = 0; nt < 4; nt++)
                    mma_tf32(acc[mt][nt], a[mt], b[nt]);
        }

        #pragma unroll
        for (int mt = 0; mt < 2; mt++)
            #pragma unroll
            for (int nt = 0; nt < 4; nt++) {
                prs[mt][0] += __expf(acc[mt][nt][0] * SCALE_)
                            + __expf(acc[mt][nt][1] * SCALE_);
                prs[mt][1] += __expf(acc[mt][nt][2] * SCALE_)
                            + __expf(acc[mt][nt][3] * SCALE_);
            }
        __syncthreads();
    }

    #pragma unroll
    for (int mt = 0; mt < 2; mt++)
        #pragma unroll
        for (int h = 0; h < 2; h++) {
            prs[mt][h] += __shfl_xor_sync(0xffffffffu, prs[mt][h], 1);
            prs[mt][h] += __shfl_xor_sync(0xffffffffu, prs[mt][h], 2);
        }
    if (qc == 0) {
        #pragma unroll
        for (int mt = 0; mt < 2; mt++) {
            prt[(warp & 1) * 128 + wm + mt * 16 + qr]     = prs[mt][0];
            prt[(warp & 1) * 128 + wm + mt * 16 + qr + 8] = prs[mt][1];
        }
    }
    __syncthreads();
    if (t < 128)
        rowsum[(size_t)z * S_ + row0 + t] = prt[t] + prt[128 + t];
}

// ---------------------------------------------------------------------------
// Pass B: BM=128, warp tile 16m x 64j. QK^T fragments -> PV A-fragments via
// intra-warp shuffles (no Ps smem). K/V double-buffered, 2 CTAs/SM.
// ---------------------------------------------------------------------------
#define AK_ST (64 * 68)
#define AV_ST (64 * 72)

__global__ __launch_bounds__(256, 2)
void attn_ctx_kernel(const float* __restrict__ Q, const float* __restrict__ K,
                     const float* __restrict__ V, const float* __restrict__ rowsum,
                     float* __restrict__ attn, float* __restrict__ C) {
    extern __shared__ float sm[];
    float* Qs = sm;                          // [128][68]
    float* Ks = sm + 128 * 68;               // 2 x [64][68]
    float* Vs = sm + 128 * 68 + 2 * AK_ST;   // 2 x [64][72]

    const int z = blockIdx.y;
    const size_t ho = (size_t)(z >> 4) * S_ * D_ + (size_t)(z & 15) * DH_;
    const float* Qg = Q + ho;
    const float* Kg = K + ho;
    const float* Vg = V + ho;
    float* Ob = attn + (size_t)z * S_ * S_;
    float* Cg = C + ho;
    const int t = threadIdx.x;
    const int row0 = blockIdx.x * 128;
    const uint32_t qsb = (uint32_t)__cvta_generic_to_shared(Qs);
    const uint32_t ksb = (uint32_t)__cvta_generic_to_shared(Ks);
    const uint32_t vsb = (uint32_t)__cvta_generic_to_shared(Vs);

    #pragma unroll
    for (int i = 0; i < 8; i++) {
        int idx = t + i * 256;
        int m = idx >> 4, c = idx & 15;
        cpa16(qsb + (uint32_t)((m * 68 + c * 4) * 4),
              Qg + (size_t)(row0 + m) * D_ + c * 4);
    }
    #pragma unroll
    for (int i = 0; i < 4; i++) {
        int idx = t + i * 256;
        int n = idx >> 4, c = idx & 15;
        cpa16(ksb + (uint32_t)((n * 68 + c * 4) * 4), Kg + (size_t)n * D_ + c * 4);
        cpa16(vsb + (uint32_t)((n * 72 + c * 4) * 4), Vg + (size_t)n * D_ + c * 4);
    }
    cp_commit();

    const int lane = t & 31, warp = t >> 5;
    const int wm = warp * 16;
    const int qr = lane >> 2, qc = lane & 3;
    const int sel = qc & 1;
    const int s0 = (lane & ~3) | (qc >> 1);

    const float inv0 = 1.0f / rowsum[(size_t)z * S_ + row0 + wm + qr];
    const float inv1 = 1.0f / rowsum[(size_t)z * S_ + row0 + wm + qr + 8];

    float ctx[8][4] = {};

    for (int jt = 0; jt < 16; jt++) {
        const int j0 = jt * 64;
        if (jt < 15) {
            const int st = (jt + 1) & 1;
            #pragma unroll
            for (int i = 0; i < 4; i++) {
                int idx = t + i * 256;
                int n = idx >> 4, c = idx & 15;
                cpa16(ksb + (uint32_t)((st * AK_ST + n * 68 + c * 4) * 4),
                      Kg + (size_t)(j0 + 64 + n) * D_ + c * 4);
                cpa16(vsb + (uint32_t)((st * AV_ST + n * 72 + c * 4) * 4),
                      Vg + (size_t)(j0 + 64 + n) * D_ + c * 4);
            }
            cp_commit();
            cp_wait1();
        } else {
            cp_wait0();
        }
        __syncthreads();

        const float* ks_ = Ks + (jt & 1) * AK_ST;
        const float* vs_ = Vs + (jt & 1) * AV_ST;

        // QK^T: 16m x 64j per warp
        float p[8][4] = {};
        #pragma unroll
        for (int ks = 0; ks < 8; ks++) {
            const int kb = ks * 8;
            float a[4];
            const float* ap = Qs + (wm + qr) * 68 + kb + qc;
            a[0] = ap[0];       a[1] = ap[8 * 68];
            a[2] = ap[4];       a[3] = ap[8 * 68 + 4];
            #pragma unroll
            for (int nt = 0; nt < 8; nt++) {
                const float* bp = ks_ + (nt * 8 + qr) * 68 + kb + qc;
                float b[2] = { bp[0], bp[4] };
                mma_tf32(p[nt], a, b);
            }
        }

        // exp + normalize + write attn; keep e in p[] registers
        #pragma unroll
        for (int nt = 0; nt < 8; nt++) {
            const int cl = nt * 8 + 2 * qc;
            float e0 = __expf(p[nt][0] * SCALE_) * inv0;
            float e1 = __expf(p[nt][1] * SCALE_) * inv0;
            float e2 = __expf(p[nt][2] * SCALE_) * inv1;
            float e3 = __expf(p[nt][3] * SCALE_) * inv1;
            *(float2*)(Ob + (size_t)(row0 + wm + qr) * S_ + j0 + cl)     = make_float2(e0, e1);
            *(float2*)(Ob + (size_t)(row0 + wm + qr + 8) * S_ + j0 + cl) = make_float2(e2, e3);
            p[nt][0] = e0; p[nt][1] = e1; p[nt][2] = e2; p[nt][3] = e3;
        }

        // PV via shuffle-built A-fragments
        #pragma unroll
        for (int nt = 0; nt < 8; nt++) {
            float x0 = __shfl_sync(0xffffffffu, p[nt][0], s0);
            float x1 = __shfl_sync(0xffffffffu, p[nt][1], s0);
            float x2 = __shfl_sync(0xffffffffu, p[nt][2], s0);
            float x3 = __shfl_sync(0xffffffffu, p[nt][3], s0);
            float y0 = __shfl_sync(0xffffffffu, p[nt][0], s0 + 2);
            float y1 = __shfl_sync(0xffffffffu, p[nt][1], s0 + 2);
            float y2 = __shfl_sync(0xffffffffu, p[nt][2], s0 + 2);
            float y3 = __shfl_sync(0xffffffffu, p[nt][3], s0 + 2);
            float a[4];
            a[0] = to_tf32(sel ? x1 : x0);
            a[1] = to_tf32(sel ? x3 : x2);
            a[2] = to_tf32(sel ? y1 : y0);
            a[3] = to_tf32(sel ? y3 : y2);
            const int kb = nt * 8;
            #pragma unroll
            for (int dn = 0; dn < 8; dn++) {
                const float* bp = vs_ + (kb + qc) * 72 + dn * 8 + qr;
                float b[2] = { bp[0], bp[4 * 72] };
                mma_tf32(ctx[dn], a, b);
            }
        }
        __syncthreads();
    }

    #pragma unroll
    for (int dn = 0; dn < 8; dn++) {
        const int r = row0 + wm + qr;
        const int c = dn * 8 + 2 * qc;
        float v0 = to_tf32(ctx[dn][0]), v1 = to_tf32(ctx[dn][1]);
        float v2 = to_tf32(ctx[dn][2]), v3 = to_tf32(ctx[dn][3]);
        *(float2*)(Cg + (size_t)r * D_ + c)       = make_float2(v0, v1);
        *(float2*)(Cg + (size_t)(r + 8) * D_ + c) = make_float2(v2, v3);
    }
}

// ---------------------------------------------------------------------------
// Launch: tf32 prepass, projections, rowsum forked parallel to V projection.
// ---------------------------------------------------------------------------
extern "C" void kernel_launch(void* const* d_in, const int* in_sizes, int n_in,
                              void* d_out, int out_size) {
    const float* query = (const float*)d_in[0];
    const float* key   = (const float*)d_in[1];
    const float* value = (const float*)d_in[2];
    const float* Wq    = (const float*)d_in[3];
    const float* bq    = (const float*)d_in[4];
    const float* Wk    = (const float*)d_in[5];
    const float* bk    = (const float*)d_in[6];
    const float* Wv    = (const float*)d_in[7];
    const float* bv    = (const float*)d_in[8];
    const float* Wo    = (const float*)d_in[9];
    const float* bo    = (const float*)d_in[10];
    float* out = (float*)d_out;

    float *q_ptr, *k_ptr, *v_ptr, *ctx_ptr, *rs_ptr, *fb_ptr;
    float *rxq, *rxk, *rxv, *rw;
    cudaGetSymbolAddress((void**)&q_ptr,   g_q);
    cudaGetSymbolAddress((void**)&k_ptr,   g_k);
    cudaGetSymbolAddress((void**)&v_ptr,   g_v);
    cudaGetSymbolAddress((void**)&ctx_ptr, g_ctx);
    cudaGetSymbolAddress((void**)&rs_ptr,  g_rowsum);
    cudaGetSymbolAddress((void**)&fb_ptr,  g_attn_fb);
    cudaGetSymbolAddress((void**)&rxq,     g_rxq);
    cudaGetSymbolAddress((void**)&rxk,     g_rxk);
    cudaGetSymbolAddress((void**)&rxv,     g_rxv);
    cudaGetSymbolAddress((void**)&rw,      g_rw);

    const long long bhss = (long long)B_ * H_ * S_ * S_;
    float* attn_out = fb_ptr;
    if ((long long)out_size >= (long long)BSD_ + bhss)
        attn_out = out + BSD_;

    const int proj_smem = (3 * PA_ST + 3 * PB_ST) * 4;                  // 107520
    const int rs_smem   = (128 * 68 + 2 * RK_ST + 256) * 4;             // 70656
    const int ac_smem   = (128 * 68 + 2 * AK_ST + 2 * AV_ST) * 4;       // 106496
    cudaFuncSetAttribute(proj_gemm<true>,  cudaFuncAttributeMaxDynamicSharedMemorySize, proj_smem);
    cudaFuncSetAttribute(proj_gemm<false>, cudaFuncAttributeMaxDynamicSharedMemorySize, proj_smem);
    cudaFuncSetAttribute(rowsum_kernel,    cudaFuncAttributeMaxDynamicSharedMemorySize, rs_smem);
    cudaFuncSetAttribute(attn_ctx_kernel,  cudaFuncAttributeMaxDynamicSharedMemorySize, ac_smem);

    dim3 gproj(D_ / 128, (B_ * S_) / 128);          // (8, 64)
    dim3 grs(S_ / 128, B_ * H_);                    // (8, 128)

    // tf32 prepass: inputs + all four weights (memory-bound, ~45us total)
    const int n4x = BSD_ / 4, n4w = (D_ * D_) / 4;
    cvt_rna_kernel<<<(n4x + 255) / 256, 256>>>((const float4*)query, (float4*)rxq, n4x);
    cvt_rna_kernel<<<(n4x + 255) / 256, 256>>>((const float4*)key,   (float4*)rxk, n4x);
    cvt_rna_kernel<<<(n4x + 255) / 256, 256>>>((const float4*)value, (float4*)rxv, n4x);
    cvt_rna_kernel<<<(n4w + 255) / 256, 256>>>((const float4*)Wq, (float4*)(rw + 0ll * D_ * D_), n4w);
    cvt_rna_kernel<<<(n4w + 255) / 256, 256>>>((const float4*)Wk, (float4*)(rw + 1ll * D_ * D_), n4w);
    cvt_rna_kernel<<<(n4w + 255) / 256, 256>>>((const float4*)Wv, (float4*)(rw + 2ll * D_ * D_), n4w);
    cvt_rna_kernel<<<(n4w + 255) / 256, 256>>>((const float4*)Wo, (float4*)(rw + 3ll * D_ * D_), n4w);

    // Q and K projections (main stream)
    proj_gemm<true><<<gproj, 256, proj_smem>>>(rxq, rw + 0ll * D_ * D_, bq, q_ptr);
    proj_gemm<true><<<gproj, 256, proj_smem>>>(rxk, rw + 1ll * D_ * D_, bk, k_ptr);

    // Fork: rowsum (needs Q,K) on side stream, V projection on main stream.
    cudaStream_t s2;
    cudaEvent_t evFork, evJoin;
    cudaStreamCreateWithFlags(&s2, cudaStreamNonBlocking);
    cudaEventCreateWithFlags(&evFork, cudaEventDisableTiming);
    cudaEventCreateWithFlags(&evJoin, cudaEventDisableTiming);

    cudaEventRecord(evFork, 0);
    cudaStreamWaitEvent(s2, evFork, 0);
    rowsum_kernel<<<grs, 256, rs_smem, s2>>>(q_ptr, k_ptr, rs_ptr);
    cudaEventRecord(evJoin, s2);

    proj_gemm<true><<<gproj, 256, proj_smem>>>(rxv, rw + 2ll * D_ * D_, bv, v_ptr);
    cudaStreamWaitEvent(0, evJoin, 0);

    // Pass B + O projection (main stream). ctx is pre-rounded by attn_ctx.
    dim3 gac(S_ / 128, B_ * H_);                    // (8, 128)
    attn_ctx_kernel<<<gac, 256, ac_smem>>>(q_ptr, k_ptr, v_ptr, rs_ptr, attn_out, ctx_ptr);
    proj_gemm<false><<<gproj, 256, proj_smem>>>(ctx_ptr, rw + 3ll * D_ * D_, bo, out);
}

// round 15
// speedup vs baseline: 1.7209x; 1.7209x over previous
#include <cuda_runtime.h>
#include <cuda_fp16.h>
#include <cstdint>

#define B_  8
#define S_  1024
#define D_  1024
#define H_  16
#define DH_ 64
#define BSD_ (B_ * S_ * D_)
#define BHS_ (B_ * H_ * S_)
#define SCALE_ 0.125f

// ---------------------------------------------------------------------------
// Scratch (__device__ globals; alloc-free rule)
// ---------------------------------------------------------------------------
__device__ __half g_q[BSD_];            // Q projection output (fp16)
__device__ __half g_k[BSD_];
__device__ __half g_v[BSD_];
__device__ __half g_ctx[BSD_];
__device__ __half g_xq[BSD_];           // fp16-converted inputs
__device__ __half g_xk[BSD_];
__device__ __half g_xv[BSD_];
__device__ __half g_wp[4ll * D_ * D_];  // k-pair-packed fp16 weights
__device__ __half g_vp[BSD_];           // token-pair-packed V
__device__ float  g_rowsum[BHS_];
__device__ float  g_attn_fb[(size_t)B_ * H_ * S_ * S_];

// ---------------------------------------------------------------------------
// Helpers
// ---------------------------------------------------------------------------
__device__ __forceinline__ uint32_t h2u(__half2 h) { return *(uint32_t*)&h; }

__device__ __forceinline__ void mma_f16(float c[4], const uint32_t a[4],
                                        const uint32_t b[2]) {
    asm volatile(
        "mma.sync.aligned.m16n8k16.row.col.f32.f16.f16.f32 "
        "{%0,%1,%2,%3}, {%4,%5,%6,%7}, {%8,%9}, {%0,%1,%2,%3};"
        : "+f"(c[0]), "+f"(c[1]), "+f"(c[2]), "+f"(c[3])
        : "r"(a[0]), "r"(a[1]), "r"(a[2]), "r"(a[3]), "r"(b[0]), "r"(b[1]));
}

__device__ __forceinline__ void cpa16(uint32_t dst, const void* src) {
    asm volatile("cp.async.cg.shared.global [%0], [%1], 16;\n" :: "r"(dst), "l"(src));
}
__device__ __forceinline__ void cp_commit() { asm volatile("cp.async.commit_group;\n"); }
__device__ __forceinline__ void cp_wait0()  { asm volatile("cp.async.wait_group 0;\n"); }
__device__ __forceinline__ void cp_wait1()  { asm volatile("cp.async.wait_group 1;\n"); }
__device__ __forceinline__ void cp_wait2()  { asm volatile("cp.async.wait_group 2;\n"); }

// ---------------------------------------------------------------------------
// Prepass kernels (memory-bound)
// ---------------------------------------------------------------------------
// fp32 -> fp16 elementwise
__global__ __launch_bounds__(256)
void cvt_h_kernel(const float4* __restrict__ in, __half2* __restrict__ out, int n4) {
    int i = blockIdx.x * 256 + threadIdx.x;
    if (i < n4) {
        float4 v = in[i];
        out[2 * i]     = __floats2half2_rn(v.x, v.y);
        out[2 * i + 1] = __floats2half2_rn(v.z, v.w);
    }
}

// W[k][n] fp32 -> Wp[k/2][n] half2{W[2k'][n], W[2k'+1][n]}
__global__ __launch_bounds__(256)
void pack_w_kernel(const float* __restrict__ w, __half2* __restrict__ wp) {
    int idx = blockIdx.x * 256 + threadIdx.x;     // 512*256 threads
    int kp = idx >> 8, c = idx & 255;             // c covers 4 n
    float4 lo = *(const float4*)(w + (size_t)(2 * kp) * D_ + c * 4);
    float4 hi = *(const float4*)(w + (size_t)(2 * kp + 1) * D_ + c * 4);
    __half2* o = wp + (size_t)kp * D_ + c * 4;
    o[0] = __floats2half2_rn(lo.x, hi.x);
    o[1] = __floats2half2_rn(lo.y, hi.y);
    o[2] = __floats2half2_rn(lo.z, hi.z);
    o[3] = __floats2half2_rn(lo.w, hi.w);
}

// V fp16 [b*1024+t][1024] -> Vp half2 [(b*512+t/2)][1024] = {V[2t'], V[2t'+1]}
__global__ __launch_bounds__(256)
void vpack_kernel(const __half* __restrict__ v, __half2* __restrict__ vp) {
    int idx = blockIdx.x * 256 + threadIdx.x;     // 4096*256 threads
    int row = idx >> 8, c = idx & 255;            // c covers 4 cols
    int b = row >> 9, j = row & 511;
    const __half* lo = v + ((size_t)(b * 1024 + 2 * j)) * D_ + c * 4;
    const __half* hi = lo + D_;
    __half l[4], h[4];
    *(uint2*)l = *(const uint2*)lo;
    *(uint2*)h = *(const uint2*)hi;
    __half2* o = vp + (size_t)row * D_ + c * 4;
    o[0] = __halves2half2(l[0], h[0]);
    o[1] = __halves2half2(l[1], h[1]);
    o[2] = __halves2half2(l[2], h[2]);
    o[3] = __halves2half2(l[3], h[3]);
}

// ---------------------------------------------------------------------------
// Projection GEMM (fp16 MMA): C[8192,1024] = A @ W + bias
// BM=128, BN=128, BK=64, 3-stage cp.async. A: fp16 [m][k]; W: packed Wp.
// ---------------------------------------------------------------------------
#define PA_H (128 * 72)     // A stage halves ([128][72] padded)
#define PB_W (32 * 136)     // B stage words  ([32 k'][136] padded)
#define PST_B (PA_H * 2 + PB_W * 4)   // stage bytes = 35840

__device__ __forceinline__ void projh_load_stage(
    uint32_t asb, uint32_t bsb, const __half* A, const __half* Wp,
    int row0, int col0, int k0, int st, int t) {
    #pragma unroll
    for (int i = 0; i < 4; i++) {
        int idx = t + i * 256;
        int m = idx >> 3, c = idx & 7;
        cpa16(asb + (uint32_t)((st * PA_H + m * 72 + c * 8) * 2),
              A + (size_t)(row0 + m) * D_ + k0 + c * 8);
    }
    const int k0h = k0 >> 1;
    #pragma unroll
    for (int i = 0; i < 4; i++) {
        int idx = t + i * 256;
        int kk = idx >> 5, c = idx & 31;
        cpa16(bsb + (uint32_t)((st * PB_W + kk * 136 + c * 4) * 4),
              Wp + 2 * ((size_t)(k0h + kk) * D_ + col0 + c * 4));
    }
    cp_commit();
}

template<bool HALF_OUT>
__global__ __launch_bounds__(256)
void proj_gemm_h(const __half* __restrict__ A, const __half* __restrict__ Wp,
                 const float* __restrict__ bias, void* __restrict__ Cv) {
    extern __shared__ char smc[];
    __half*    As = (__half*)smc;                       // 3 stages of PA_H
    uint32_t*  Bs = (uint32_t*)(smc + 3 * PA_H * 2);    // 3 stages of PB_W
    const int t = threadIdx.x;
    const int row0 = blockIdx.y * 128, col0 = blockIdx.x * 128;
    const uint32_t asb = (uint32_t)__cvta_generic_to_shared(As);
    const uint32_t bsb = (uint32_t)__cvta_generic_to_shared(Bs);

    const int lane = t & 31, warp = t >> 5;
    const int wm = (warp >> 2) * 64, wn = (warp & 3) * 32;
    const int qr = lane >> 2, qc = lane & 3;

    float acc[4][4][4] = {};

    projh_load_stage(asb, bsb, A, Wp, row0, col0, 0, 0, t);
    projh_load_stage(asb, bsb, A, Wp, row0, col0, 64, 1, t);

    for (int kt = 0; kt < 16; kt++) {
        if (kt < 14) {
            projh_load_stage(asb, bsb, A, Wp, row0, col0, (kt + 2) * 64, (kt + 2) % 3, t);
            cp_wait2();
        } else if (kt == 14) {
            cp_wait1();
        } else {
            cp_wait0();
        }
        __syncthreads();

        const __half*   as = As + (kt % 3) * PA_H;
        const uint32_t* bs = Bs + (kt % 3) * PB_W;
        #pragma unroll
        for (int ks = 0; ks < 4; ks++) {
            uint32_t a[4][4], b[4][2];
            #pragma unroll
            for (int mt = 0; mt < 4; mt++) {
                const __half* ap = as + (wm + mt * 16 + qr) * 72 + ks * 16 + 2 * qc;
                a[mt][0] = *(const uint32_t*)ap;
                a[mt][1] = *(const uint32_t*)(ap + 8 * 72);
                a[mt][2] = *(const uint32_t*)(ap + 8);
                a[mt][3] = *(const uint32_t*)(ap + 8 * 72 + 8);
            }
            #pragma unroll
            for (int nt = 0; nt < 4; nt++) {
                const uint32_t* bp = bs + (ks * 8 + qc) * 136 + wn + nt * 8 + qr;
                b[nt][0] = bp[0];
                b[nt][1] = bp[4 * 136];
            }
            #pragma unroll
            for (int mt = 0; mt < 4; mt++)
                #pragma unroll
                for (int nt = 0; nt < 4; nt++)
                    mma_f16(acc[mt][nt], a[mt], b[nt]);
        }
        __syncthreads();
    }

    #pragma unroll
    for (int mt = 0; mt < 4; mt++) {
        #pragma unroll
        for (int nt = 0; nt < 4; nt++) {
            const int r = row0 + wm + mt * 16 + qr;
            const int c = col0 + wn + nt * 8 + 2 * qc;
            const float b0 = bias[c], b1 = bias[c + 1];
            float v0 = acc[mt][nt][0] + b0, v1 = acc[mt][nt][1] + b1;
            float v2 = acc[mt][nt][2] + b0, v3 = acc[mt][nt][3] + b1;
            if (HALF_OUT) {
                __half* C = (__half*)Cv;
                *(__half2*)(C + (size_t)r * D_ + c)       = __floats2half2_rn(v0, v1);
                *(__half2*)(C + (size_t)(r + 8) * D_ + c) = __floats2half2_rn(v2, v3);
            } else {
                float* C = (float*)Cv;
                *(float2*)(C + (size_t)r * D_ + c)       = make_float2(v0, v1);
                *(float2*)(C + (size_t)(r + 8) * D_ + c) = make_float2(v2, v3);
            }
        }
    }
}

// ---------------------------------------------------------------------------
// Pass A: rowsum (fp16 QK^T). Q 128 rows resident; K 64-row double-buffered.
// ---------------------------------------------------------------------------
#define RQ_H (128 * 72)
#define RK_H (64 * 72)

__global__ __launch_bounds__(256, 2)
void rowsum_kernel(const __half* __restrict__ Q, const __half* __restrict__ K,
                   float* __restrict__ rowsum) {
    extern __shared__ char smc[];
    __half* Qs = (__half*)smc;
    __half* Ks = (__half*)(smc + RQ_H * 2);
    float* prt = (float*)(smc + RQ_H * 2 + 2 * RK_H * 2);

    const int z = blockIdx.y;
    const size_t ho = (size_t)(z >> 4) * S_ * D_ + (size_t)(z & 15) * DH_;
    const __half* Qg = Q + ho;
    const __half* Kg = K + ho;
    const int t = threadIdx.x;
    const int row0 = blockIdx.x * 128;
    const uint32_t qsb = (uint32_t)__cvta_generic_to_shared(Qs);
    const uint32_t ksb = (uint32_t)__cvta_generic_to_shared(Ks);

    prt[t] = 0.f;

    #pragma unroll
    for (int i = 0; i < 4; i++) {
        int idx = t + i * 256;
        int m = idx >> 3, c = idx & 7;
        cpa16(qsb + (uint32_t)((m * 72 + c * 8) * 2),
              Qg + (size_t)(row0 + m) * D_ + c * 8);
    }
    #pragma unroll
    for (int i = 0; i < 2; i++) {
        int idx = t + i * 256;
        int n = idx >> 3, c = idx & 7;
        cpa16(ksb + (uint32_t)((n * 72 + c * 8) * 2),
              Kg + (size_t)n * D_ + c * 8);
    }
    cp_commit();

    const int lane = t & 31, warp = t >> 5;
    const int wm = (warp >> 1) * 32;
    const int wj = (warp & 1) * 32;
    const int qr = lane >> 2, qc = lane & 3;

    float prs[2][2] = {};

    for (int jt = 0; jt < 16; jt++) {
        if (jt < 15) {
            const int st = (jt + 1) & 1;
            #pragma unroll
            for (int i = 0; i < 2; i++) {
                int idx = t + i * 256;
                int n = idx >> 3, c = idx & 7;
                cpa16(ksb + (uint32_t)((st * RK_H + n * 72 + c * 8) * 2),
                      Kg + (size_t)((jt + 1) * 64 + n) * D_ + c * 8);
            }
            cp_commit();
            cp_wait1();
        } else {
            cp_wait0();
        }
        __syncthreads();

        const __half* ks_ = Ks + (jt & 1) * RK_H;
        float acc[2][4][4] = {};
        #pragma unroll
        for (int ks = 0; ks < 4; ks++) {
            uint32_t a[2][4], b[4][2];
            #pragma unroll
            for (int mt = 0; mt < 2; mt++) {
                const __half* ap = Qs + (wm + mt * 16 + qr) * 72 + ks * 16 + 2 * qc;
                a[mt][0] = *(const uint32_t*)ap;
                a[mt][1] = *(const uint32_t*)(ap + 8 * 72);
                a[mt][2] = *(const uint32_t*)(ap + 8);
                a[mt][3] = *(const uint32_t*)(ap + 8 * 72 + 8);
            }
            #pragma unroll
            for (int nt = 0; nt < 4; nt++) {
                const __half* bp = ks_ + (wj + nt * 8 + qr) * 72 + ks * 16 + 2 * qc;
                b[nt][0] = *(const uint32_t*)bp;
                b[nt][1] = *(const uint32_t*)(bp + 8);
            }
            #pragma unroll
            for (int mt = 0; mt < 2; mt++)
                #pragma unroll
                for (int nt = 0; nt < 4; nt++)
                    mma_f16(acc[mt][nt], a[mt], b[nt]);
        }

        #pragma unroll
        for (int mt = 0; mt < 2; mt++)
            #pragma unroll
            for (int nt = 0; nt < 4; nt++) {
                prs[mt][0] += __expf(acc[mt][nt][0] * SCALE_)
                            + __expf(acc[mt][nt][1] * SCALE_);
                prs[mt][1] += __expf(acc[mt][nt][2] * SCALE_)
                            + __expf(acc[mt][nt][3] * SCALE_);
            }
        __syncthreads();
    }

    #pragma unroll
    for (int mt = 0; mt < 2; mt++)
        #pragma unroll
        for (int h = 0; h < 2; h++) {
            prs[mt][h] += __shfl_xor_sync(0xffffffffu, prs[mt][h], 1);
            prs[mt][h] += __shfl_xor_sync(0xffffffffu, prs[mt][h], 2);
        }
    if (qc == 0) {
        #pragma unroll
        for (int mt = 0; mt < 2; mt++) {
            prt[(warp & 1) * 128 + wm + mt * 16 + qr]     = prs[mt][0];
            prt[(warp & 1) * 128 + wm + mt * 16 + qr + 8] = prs[mt][1];
        }
    }
    __syncthreads();
    if (t < 128)
        rowsum[(size_t)z * S_ + row0 + t] = prt[t] + prt[128 + t];
}

// ---------------------------------------------------------------------------
// Pass B: fp16 QK^T -> exp/normalize -> attn store -> PV with register-only
// fragment handoff. BM=128, warp tile 16m x 64j. K / packed-V double-buffered.
// ---------------------------------------------------------------------------
#define AQ_H (128 * 72)
#define AK_H (64 * 72)
#define AV_W (32 * 72)      // Vp tile words ([32 j'][72])

__global__ __launch_bounds__(256, 2)
void attn_ctx_kernel(const __half* __restrict__ Q, const __half* __restrict__ K,
                     const __half* __restrict__ Vp, const float* __restrict__ rowsum,
                     float* __restrict__ attn, __half* __restrict__ C) {
    extern __shared__ char smc[];
    __half*   Qs = (__half*)smc;
    __half*   Ks = (__half*)(smc + AQ_H * 2);
    uint32_t* Vs = (uint32_t*)(smc + AQ_H * 2 + 2 * AK_H * 2);

    const int z = blockIdx.y;
    const int bb = z >> 4, hh = z & 15;
    const size_t ho = (size_t)bb * S_ * D_ + (size_t)hh * DH_;
    const __half* Qg = Q + ho;
    const __half* Kg = K + ho;
    const __half* Vg = Vp + 2 * ((size_t)(bb * 512) * D_ + hh * DH_);
    float* Ob = attn + (size_t)z * S_ * S_;
    __half* Cg = C + ho;
    const int t = threadIdx.x;
    const int row0 = blockIdx.x * 128;
    const uint32_t qsb = (uint32_t)__cvta_generic_to_shared(Qs);
    const uint32_t ksb = (uint32_t)__cvta_generic_to_shared(Ks);
    const uint32_t vsb = (uint32_t)__cvta_generic_to_shared(Vs);

    #pragma unroll
    for (int i = 0; i < 4; i++) {
        int idx = t + i * 256;
        int m = idx >> 3, c = idx & 7;
        cpa16(qsb + (uint32_t)((m * 72 + c * 8) * 2),
              Qg + (size_t)(row0 + m) * D_ + c * 8);
    }
    #pragma unroll
    for (int i = 0; i < 2; i++) {
        int idx = t + i * 256;
        int n = idx >> 3, c = idx & 7;
        cpa16(ksb + (uint32_t)((n * 72 + c * 8) * 2),
              Kg + (size_t)n * D_ + c * 8);
    }
    #pragma unroll
    for (int i = 0; i < 2; i++) {
        int idx = t + i * 256;
        int n = idx >> 4, c = idx & 15;
        cpa16(vsb + (uint32_t)((n * 72 + c * 4) * 4),
              Vg + (size_t)n * 2 * D_ + c * 8);
    }
    cp_commit();

    const int lane = t & 31, warp = t >> 5;
    const int wm = warp * 16;
    const int qr = lane >> 2, qc = lane & 3;

    const float inv0 = 1.0f / rowsum[(size_t)z * S_ + row0 + wm + qr];
    const float inv1 = 1.0f / rowsum[(size_t)z * S_ + row0 + wm + qr + 8];

    float ctx[8][4] = {};

    for (int jt = 0; jt < 16; jt++) {
        const int j0 = jt * 64;
        if (jt < 15) {
            const int st = (jt + 1) & 1;
            #pragma unroll
            for (int i = 0; i < 2; i++) {
                int idx = t + i * 256;
                int n = idx >> 3, c = idx & 7;
                cpa16(ksb + (uint32_t)((st * AK_H + n * 72 + c * 8) * 2),
                      Kg + (size_t)(j0 + 64 + n) * D_ + c * 8);
            }
            #pragma unroll
            for (int i = 0; i < 2; i++) {
                int idx = t + i * 256;
                int n = idx >> 4, c = idx & 15;
                cpa16(vsb + (uint32_t)((st * AV_W + n * 72 + c * 4) * 4),
                      Vg + (size_t)((jt + 1) * 32 + n) * 2 * D_ + c * 8);
            }
            cp_commit();
            cp_wait1();
        } else {
            cp_wait0();
        }
        __syncthreads();

        const __half*   ks_ = Ks + (jt & 1) * AK_H;
        const uint32_t* vs_ = Vs + (jt & 1) * AV_W;

        // QK^T: 16m x 64j per warp, k = d = 64 (4 mma-k-steps)
        float p[8][4] = {};
        #pragma unroll
        for (int ks = 0; ks < 4; ks++) {
            uint32_t a[4];
            const __half* ap = Qs + (wm + qr) * 72 + ks * 16 + 2 * qc;
            a[0] = *(const uint32_t*)ap;
            a[1] = *(const uint32_t*)(ap + 8 * 72);
            a[2] = *(const uint32_t*)(ap + 8);
            a[3] = *(const uint32_t*)(ap + 8 * 72 + 8);
            #pragma unroll
            for (int nt = 0; nt < 8; nt++) {
                const __half* bp = ks_ + (nt * 8 + qr) * 72 + ks * 16 + 2 * qc;
                uint32_t b[2] = { *(const uint32_t*)bp, *(const uint32_t*)(bp + 8) };
                mma_f16(p[nt], a, b);
            }
        }

        // exp + normalize + write attn (fp32); keep normalized e in p[]
        #pragma unroll
        for (int nt = 0; nt < 8; nt++) {
            const int cl = nt * 8 + 2 * qc;
            float e0 = __expf(p[nt][0] * SCALE_) * inv0;
            float e1 = __expf(p[nt][1] * SCALE_) * inv0;
            float e2 = __expf(p[nt][2] * SCALE_) * inv1;
            float e3 = __expf(p[nt][3] * SCALE_) * inv1;
            *(float2*)(Ob + (size_t)(row0 + wm + qr) * S_ + j0 + cl)     = make_float2(e0, e1);
            *(float2*)(Ob + (size_t)(row0 + wm + qr + 8) * S_ + j0 + cl) = make_float2(e2, e3);
            p[nt][0] = e0; p[nt][1] = e1; p[nt][2] = e2; p[nt][3] = e3;
        }

        // PV: A-fragments directly from this thread's p registers (no shuffle!)
        #pragma unroll
        for (int ks = 0; ks < 4; ks++) {
            uint32_t a[4];
            a[0] = h2u(__floats2half2_rn(p[2 * ks][0],     p[2 * ks][1]));
            a[1] = h2u(__floats2half2_rn(p[2 * ks][2],     p[2 * ks][3]));
            a[2] = h2u(__floats2half2_rn(p[2 * ks + 1][0], p[2 * ks + 1][1]));
            a[3] = h2u(__floats2half2_rn(p[2 * ks + 1][2], p[2 * ks + 1][3]));
            #pragma unroll
            for (int dn = 0; dn < 8; dn++) {
                const uint32_t* bp = vs_ + (ks * 8 + qc) * 72 + dn * 8 + qr;
                uint32_t b[2] = { bp[0], bp[4 * 72] };
                mma_f16(ctx[dn], a, b);
            }
        }
        __syncthreads();
    }

    // ctx -> fp16 for O projection
    #pragma unroll
    for (int dn = 0; dn < 8; dn++) {
        const int r = row0 + wm + qr;
        const int c = dn * 8 + 2 * qc;
        *(__half2*)(Cg + (size_t)r * D_ + c)       = __floats2half2_rn(ctx[dn][0], ctx[dn][1]);
        *(__half2*)(Cg + (size_t)(r + 8) * D_ + c) = __floats2half2_rn(ctx[dn][2], ctx[dn][3]);
    }
}

// ---------------------------------------------------------------------------
// Launch
// ---------------------------------------------------------------------------
extern "C" void kernel_launch(void* const* d_in, const int* in_sizes, int n_in,
                              void* d_out, int out_size) {
    const float* query = (const float*)d_in[0];
    const float* key   = (const float*)d_in[1];
    const float* value = (const float*)d_in[2];
    const float* Wq    = (const float*)d_in[3];
    const float* bq    = (const float*)d_in[4];
    const float* Wk    = (const float*)d_in[5];
    const float* bk    = (const float*)d_in[6];
    const float* Wv    = (const float*)d_in[7];
    const float* bv    = (const float*)d_in[8];
    const float* Wo    = (const float*)d_in[9];
    const float* bo    = (const float*)d_in[10];
    float* out = (float*)d_out;

    __half *q_ptr, *k_ptr, *v_ptr, *ctx_ptr, *xq, *xk, *xv, *wp, *vp;
    float *rs_ptr, *fb_ptr;
    cudaGetSymbolAddress((void**)&q_ptr,   g_q);
    cudaGetSymbolAddress((void**)&k_ptr,   g_k);
    cudaGetSymbolAddress((void**)&v_ptr,   g_v);
    cudaGetSymbolAddress((void**)&ctx_ptr, g_ctx);
    cudaGetSymbolAddress((void**)&xq,      g_xq);
    cudaGetSymbolAddress((void**)&xk,      g_xk);
    cudaGetSymbolAddress((void**)&xv,      g_xv);
    cudaGetSymbolAddress((void**)&wp,      g_wp);
    cudaGetSymbolAddress((void**)&vp,      g_vp);
    cudaGetSymbolAddress((void**)&rs_ptr,  g_rowsum);
    cudaGetSymbolAddress((void**)&fb_ptr,  g_attn_fb);

    const long long bhss = (long long)B_ * H_ * S_ * S_;
    float* attn_out = fb_ptr;
    if ((long long)out_size >= (long long)BSD_ + bhss)
        attn_out = out + BSD_;

    const int proj_smem = 3 * PST_B;                                  // 107520
    const int rs_smem   = RQ_H * 2 + 2 * RK_H * 2 + 256 * 4;          // 37888
    const int ac_smem   = AQ_H * 2 + 2 * AK_H * 2 + 2 * AV_W * 4;     // 55296
    cudaFuncSetAttribute(proj_gemm_h<true>,  cudaFuncAttributeMaxDynamicSharedMemorySize, proj_smem);
    cudaFuncSetAttribute(proj_gemm_h<false>, cudaFuncAttributeMaxDynamicSharedMemorySize, proj_smem);
    cudaFuncSetAttribute(rowsum_kernel,      cudaFuncAttributeMaxDynamicSharedMemorySize, rs_smem);
    cudaFuncSetAttribute(attn_ctx_kernel,    cudaFuncAttributeMaxDynamicSharedMemorySize, ac_smem);

    // Prepass: fp16 conversions + weight packing
    const int n4x = BSD_ / 4;
    cvt_h_kernel<<<n4x / 256, 256>>>((const float4*)query, (__half2*)xq, n4x);
    cvt_h_kernel<<<n4x / 256, 256>>>((const float4*)key,   (__half2*)xk, n4x);
    cvt_h_kernel<<<n4x / 256, 256>>>((const float4*)value, (__half2*)xv, n4x);
    pack_w_kernel<<<512, 256>>>(Wq, (__half2*)(wp + 0ll * D_ * D_));
    pack_w_kernel<<<512, 256>>>(Wk, (__half2*)(wp + 1ll * D_ * D_));
    pack_w_kernel<<<512, 256>>>(Wv, (__half2*)(wp + 2ll * D_ * D_));
    pack_w_kernel<<<512, 256>>>(Wo, (__half2*)(wp + 3ll * D_ * D_));

    dim3 gproj(D_ / 128, (B_ * S_) / 128);          // (8, 64)
    dim3 grs(S_ / 128, B_ * H_);                    // (8, 128)

    // Q and K projections
    proj_gemm_h<true><<<gproj, 256, proj_smem>>>(xq, wp + 0ll * D_ * D_, bq, q_ptr);
    proj_gemm_h<true><<<gproj, 256, proj_smem>>>(xk, wp + 1ll * D_ * D_, bk, k_ptr);

    // Fork: rowsum (needs Q,K) || V projection + V pack (main stream)
    cudaStream_t s2;
    cudaEvent_t evFork, evJoin;
    cudaStreamCreateWithFlags(&s2, cudaStreamNonBlocking);
    cudaEventCreateWithFlags(&evFork, cudaEventDisableTiming);
    cudaEventCreateWithFlags(&evJoin, cudaEventDisableTiming);

    cudaEventRecord(evFork, 0);
    cudaStreamWaitEvent(s2, evFork, 0);
    rowsum_kernel<<<grs, 256, rs_smem, s2>>>(q_ptr, k_ptr, rs_ptr);
    cudaEventRecord(evJoin, s2);

    proj_gemm_h<true><<<gproj, 256, proj_smem>>>(xv, wp + 2ll * D_ * D_, bv, v_ptr);
    vpack_kernel<<<4096, 256>>>(v_ptr, (__half2*)vp);
    cudaStreamWaitEvent(0, evJoin, 0);

    // Pass B + O projection
    dim3 gac(S_ / 128, B_ * H_);                    // (8, 128)
    attn_ctx_kernel<<<gac, 256, ac_smem>>>(q_ptr, k_ptr, vp, rs_ptr, attn_out, ctx_ptr);
    proj_gemm_h<false><<<gproj, 256, proj_smem>>>(ctx_ptr, wp + 3ll * D_ * D_, bo, out);
}